// round 1
// baseline (speedup 1.0000x reference)
#include <cuda_runtime.h>
#include <math.h>

#define B_     32
#define NTOK   197
#define DIM_   384
#define HEADS_ 12
#define HD_    32
#define HID_   36
#define P_     38809        // 197*197
#define TOK_   6304         // 32*197
#define QKVN_  1152
#define MLPH_  1536
#define PIX_   1241888      // 32*38809

// ------------------------- scratch (static device globals) -------------------
__device__ float  g_h   [TOK_ * DIM_];
__device__ float  g_qkv [TOK_ * QKVN_];
__device__ float  g_attn[(size_t)B_ * HEADS_ * P_];   // softmax output a0
__device__ float  g_aexp[(size_t)B_ * HID_   * P_];
__device__ float  g_adw [(size_t)B_ * HID_   * P_];
__device__ float  g_apro[(size_t)B_ * HEADS_ * P_];   // later holds t = bn3(a)+a0
__device__ float  g_av  [TOK_ * DIM_];
__device__ float  g_x1  [TOK_ * DIM_];
__device__ float  g_m   [TOK_ * DIM_];
__device__ float  g_mlp [TOK_ * MLPH_];
__device__ double g_stats[288];     // 4 regions of 72 doubles (sum, then sumsq)
__device__ float2 g_sc  [144];      // 4 regions of 36 float2 (scale, shift)

// ------------------------------- small kernels -------------------------------
__global__ void zero_stats_k(double* st) {
    if (threadIdx.x < 288) st[threadIdx.x] = 0.0;
}

// LayerNorm of (0.5 * x) with per-channel gamma/beta. One block per token.
__global__ void ln_kernel(const float* __restrict__ x, const float* __restrict__ g,
                          const float* __restrict__ b, float* __restrict__ out) {
    int t = blockIdx.x, tid = threadIdx.x;
    const float* xr = x + (size_t)t * DIM_;
    float v0 = 0.5f * xr[tid];
    float v1 = 0.5f * xr[tid + 128];
    float v2 = 0.5f * xr[tid + 256];
    float s  = v0 + v1 + v2;
    float s2 = v0 * v0 + v1 * v1 + v2 * v2;
    for (int o = 16; o; o >>= 1) {
        s  += __shfl_down_sync(0xffffffffu, s,  o);
        s2 += __shfl_down_sync(0xffffffffu, s2, o);
    }
    __shared__ float sh[4][2];
    __shared__ float mv[2];
    if ((tid & 31) == 0) { sh[tid >> 5][0] = s; sh[tid >> 5][1] = s2; }
    __syncthreads();
    if (tid == 0) {
        float S = sh[0][0] + sh[1][0] + sh[2][0] + sh[3][0];
        float S2 = sh[0][1] + sh[1][1] + sh[2][1] + sh[3][1];
        float mean = S / (float)DIM_;
        float var  = S2 / (float)DIM_ - mean * mean;
        mv[0] = mean; mv[1] = rsqrtf(var + 1e-5f);
    }
    __syncthreads();
    float mean = mv[0], inv = mv[1];
    float* orow = out + (size_t)t * DIM_;
    orow[tid]       = (v0 - mean) * inv * g[tid]       + b[tid];
    orow[tid + 128] = (v1 - mean) * inv * g[tid + 128] + b[tid + 128];
    orow[tid + 256] = (v2 - mean) * inv * g[tid + 256] + b[tid + 256];
}

// ------------------------------- GEMM (NT) -----------------------------------
// C[M,N] = A[M,K] (row-major) * B[N,K]^T, with fused epilogues:
// epi 0: plain   epi 1: resid + 2*(acc+bias)   epi 2: gelu(acc+bias)
// epi 3: resid + 2*scale[n]*(acc+bias)
__global__ void gemm_nt(const float* __restrict__ A, const float* __restrict__ Bm,
                        float* __restrict__ C, int M, int N, int K, int epi,
                        const float* __restrict__ bias, const float* __restrict__ resid,
                        const float* __restrict__ scale) {
    __shared__ float As[64][17];
    __shared__ float Bs[64][17];
    int tx = threadIdx.x & 15, ty = threadIdx.x >> 4;
    int m0 = blockIdx.y * 64, n0 = blockIdx.x * 64;
    float acc[4][4] = {};
    for (int k0 = 0; k0 < K; k0 += 16) {
        for (int i = threadIdx.x; i < 1024; i += 256) {
            int r = i >> 4, cc = i & 15;
            As[r][cc] = (m0 + r < M) ? A[(size_t)(m0 + r) * K + k0 + cc] : 0.f;
            Bs[r][cc] = Bm[(size_t)(n0 + r) * K + k0 + cc];
        }
        __syncthreads();
#pragma unroll
        for (int k = 0; k < 16; k++) {
            float a[4], bb[4];
#pragma unroll
            for (int i = 0; i < 4; i++) a[i] = As[ty * 4 + i][k];
#pragma unroll
            for (int j = 0; j < 4; j++) bb[j] = Bs[tx * 4 + j][k];
#pragma unroll
            for (int i = 0; i < 4; i++)
#pragma unroll
                for (int j = 0; j < 4; j++) acc[i][j] = fmaf(a[i], bb[j], acc[i][j]);
        }
        __syncthreads();
    }
#pragma unroll
    for (int i = 0; i < 4; i++) {
        int m = m0 + ty * 4 + i;
        if (m >= M) continue;
#pragma unroll
        for (int j = 0; j < 4; j++) {
            int n = n0 + tx * 4 + j;
            float v = acc[i][j];
            size_t o = (size_t)m * N + n;
            if (epi == 0) {
                C[o] = v;
            } else if (epi == 1) {
                C[o] = resid[o] + 2.f * (v + bias[n]);
            } else if (epi == 2) {
                float u = v + bias[n];
                C[o] = 0.5f * u * (1.f + erff(u * 0.70710678118654752f));
            } else {
                float u = (v + bias[n]) * scale[n];
                C[o] = resid[o] + 2.f * u;
            }
        }
    }
}

// --------------------- attention logits + softmax (fused) --------------------
// One block per (b,h). K staged transposed in SMEM (odd stride 227 => no bank
// conflicts on either store or load). Q row kept in warp registers + shfl.
__global__ void attn_softmax_k(const float* __restrict__ qkv, float* __restrict__ attn) {
    int bh = blockIdx.x, b = bh / HEADS_, h = bh - b * HEADS_;
    __shared__ float Ks[32 * 227];
    const float* base = qkv + (size_t)b * NTOK * QKVN_ + h * HD_;
    for (int i = threadIdx.x; i < NTOK * 32; i += 256) {
        int m = i >> 5, d = i & 31;
        Ks[d * 227 + m] = base[(size_t)m * QKVN_ + DIM_ + d];
    }
    __syncthreads();
    int lane = threadIdx.x & 31, w = threadIdx.x >> 5;
    float* arow = attn + (size_t)bh * P_;
    for (int n = w; n < NTOK; n += 8) {
        float qreg = base[(size_t)n * QKVN_ + lane];
        float a[7] = {0, 0, 0, 0, 0, 0, 0};
#pragma unroll
        for (int d = 0; d < 32; d++) {
            float qv = __shfl_sync(0xffffffffu, qreg, d);
            const float* kc = &Ks[d * 227 + lane];
#pragma unroll
            for (int j = 0; j < 7; j++) a[j] = fmaf(qv, kc[j * 32], a[j]);
        }
#pragma unroll
        for (int j = 0; j < 7; j++) a[j] *= 0.17677669529663689f;   // 1/sqrt(32)
        if (lane >= 5) a[6] = -INFINITY;                             // m=192+lane>=197
        float mx = a[0];
#pragma unroll
        for (int j = 1; j < 7; j++) mx = fmaxf(mx, a[j]);
        for (int o = 16; o; o >>= 1) mx = fmaxf(mx, __shfl_xor_sync(0xffffffffu, mx, o));
        float sum = 0.f;
#pragma unroll
        for (int j = 0; j < 7; j++) { a[j] = expf(a[j] - mx); sum += a[j]; }
        for (int o = 16; o; o >>= 1) sum += __shfl_xor_sync(0xffffffffu, sum, o);
        float inv = 1.f / sum;
#pragma unroll
        for (int j = 0; j < 7; j++) {
            int m = lane + 32 * j;
            if (m < NTOK) arow[(size_t)n * NTOK + m] = a[j] * inv;
        }
    }
}

// ----------------------------- DLA conv kernels ------------------------------
__global__ void conv_exp_k(const float* __restrict__ attn, const float* __restrict__ w,
                           float* __restrict__ aexp) {
    __shared__ float ws[HID_ * HEADS_];
    for (int i = threadIdx.x; i < HID_ * HEADS_; i += 256) ws[i] = w[i];
    __syncthreads();
    int idx = blockIdx.x * 256 + threadIdx.x;
    if (idx >= PIX_) return;
    int b = idx / P_, p = idx - b * P_;
    const float* ap = attn + (size_t)b * HEADS_ * P_ + p;
    float in[HEADS_];
#pragma unroll
    for (int i = 0; i < HEADS_; i++) in[i] = ap[(size_t)i * P_];
    float* op = aexp + (size_t)b * HID_ * P_ + p;
#pragma unroll
    for (int o = 0; o < HID_; o++) {
        float v = 0.f;
#pragma unroll
        for (int i = 0; i < HEADS_; i++) v = fmaf(ws[o * HEADS_ + i], in[i], v);
        op[(size_t)o * P_] = v;
    }
}

// depthwise 3x3, SAME; bn1 affine + relu6 applied on-the-fly at load (zero pad)
__global__ void dwconv_k(const float* __restrict__ aexp, const float* __restrict__ dww,
                         const float2* __restrict__ sc, float* __restrict__ adw) {
    int bz = blockIdx.z, b = bz / HID_, c = bz - b * HID_;
    __shared__ float tile[34][34];
    float2 s = sc[c];
    const float* ip = aexp + ((size_t)b * HID_ + c) * P_;
    int y0 = blockIdx.y * 32, x0 = blockIdx.x * 32;
    for (int i = threadIdx.x; i < 34 * 34; i += 256) {
        int ly = i / 34, lx = i - ly * 34;
        int gy = y0 + ly - 1, gx = x0 + lx - 1;
        float v = 0.f;
        if (gy >= 0 && gy < NTOK && gx >= 0 && gx < NTOK) {
            v = fmaf(s.x, ip[gy * NTOK + gx], s.y);
            v = fminf(fmaxf(v, 0.f), 6.f);
        }
        tile[ly][lx] = v;
    }
    float w[9];
#pragma unroll
    for (int k = 0; k < 9; k++) w[k] = dww[c * 9 + k];
    __syncthreads();
    int tx = threadIdx.x & 31, tyb = threadIdx.x >> 5;
    float* op = adw + ((size_t)b * HID_ + c) * P_;
#pragma unroll
    for (int r = 0; r < 4; r++) {
        int oy = tyb + r * 8;
        int gy = y0 + oy, gx = x0 + tx;
        if (gy < NTOK && gx < NTOK) {
            float acc = 0.f;
#pragma unroll
            for (int dy = 0; dy < 3; dy++)
#pragma unroll
                for (int dx = 0; dx < 3; dx++)
                    acc = fmaf(w[dy * 3 + dx], tile[oy + dy][tx + dx], acc);
            op[gy * NTOK + gx] = acc;
        }
    }
}

// 1x1 project 36->12, bn2 affine + relu6 applied to inputs on-the-fly
__global__ void conv_pro_k(const float* __restrict__ adw, const float* __restrict__ w,
                           const float2* __restrict__ sc, float* __restrict__ apro) {
    __shared__ float ws[HEADS_ * HID_];
    __shared__ float2 scs[HID_];
    for (int i = threadIdx.x; i < HEADS_ * HID_; i += 256) ws[i] = w[i];
    if (threadIdx.x < HID_) scs[threadIdx.x] = sc[threadIdx.x];
    __syncthreads();
    int idx = blockIdx.x * 256 + threadIdx.x;
    if (idx >= PIX_) return;
    int b = idx / P_, p = idx - b * P_;
    const float* ip = adw + (size_t)b * HID_ * P_ + p;
    float in[HID_];
#pragma unroll
    for (int i = 0; i < HID_; i++) {
        float2 s = scs[i];
        float v = fmaf(s.x, ip[(size_t)i * P_], s.y);
        in[i] = fminf(fmaxf(v, 0.f), 6.f);
    }
    float* op = apro + (size_t)b * HEADS_ * P_ + p;
#pragma unroll
    for (int o = 0; o < HEADS_; o++) {
        float v = 0.f;
#pragma unroll
        for (int i = 0; i < HID_; i++) v = fmaf(ws[o * HID_ + i], in[i], v);
        op[(size_t)o * P_] = v;
    }
}

// t = bn3_scale*a_pro + bn3_shift + a0   (in place on a_pro)
__global__ void adapt_add_k(float* __restrict__ t, const float* __restrict__ a0,
                            const float2* __restrict__ sc) {
    int idx = blockIdx.x * 256 + threadIdx.x;
    if (idx >= B_ * HEADS_ * P_) return;
    int c = (idx / P_) % HEADS_;
    float2 s = sc[c];
    t[idx] = fmaf(s.x, t[idx], s.y) + a0[idx];
}

// ------------------------------ BN statistics --------------------------------
// One block per (b,c) plane; double atomics accumulate per-channel sum/sumsq.
__global__ void plane_stats(const float* __restrict__ x, double* __restrict__ sums, int C) {
    int pl = blockIdx.x, c = pl % C;
    const float* p = x + (size_t)pl * P_;
    float s = 0.f, s2 = 0.f;
    for (int i = threadIdx.x; i < P_; i += 256) {
        float v = p[i];
        s += v;
        s2 = fmaf(v, v, s2);
    }
    for (int o = 16; o; o >>= 1) {
        s  += __shfl_down_sync(0xffffffffu, s,  o);
        s2 += __shfl_down_sync(0xffffffffu, s2, o);
    }
    __shared__ float sh[8], sh2[8];
    if ((threadIdx.x & 31) == 0) { sh[threadIdx.x >> 5] = s; sh2[threadIdx.x >> 5] = s2; }
    __syncthreads();
    if (threadIdx.x == 0) {
        float S = 0.f, S2 = 0.f;
        for (int i = 0; i < 8; i++) { S += sh[i]; S2 += sh2[i]; }
        atomicAdd(&sums[c], (double)S);
        atomicAdd(&sums[C + c], (double)S2);
    }
}

__global__ void bn_fin(const double* __restrict__ sums, const float* __restrict__ g,
                       const float* __restrict__ b, float2* __restrict__ sc, int C) {
    int c = threadIdx.x;
    if (c >= C) return;
    const double cnt = 1241888.0;   // 32*197*197
    double mean = sums[c] / cnt;
    double var  = sums[C + c] / cnt - mean * mean;
    float s = (float)((double)g[c] / sqrt(var + 1e-5));
    sc[c] = make_float2(s, (float)((double)b[c] - mean * (double)s));
}

// ------------------- attn*V + final abn apply + attn output ------------------
// One block per (b,h). V staged in SMEM; applies abn affine to t, optionally
// writes the final attn tensor, and computes out[n,d] directly into [B,N,C].
__global__ void attn_av_k(const float* __restrict__ t, const float* __restrict__ qkv,
                          const float2* __restrict__ sc, float* __restrict__ attn_out,
                          float* __restrict__ av) {
    int bh = blockIdx.x, b = bh / HEADS_, h = bh - b * HEADS_;
    __shared__ float Vs[NTOK * HD_];
    __shared__ float row[NTOK];
    __shared__ float part[8][33];
    const float* vb = qkv + (size_t)b * NTOK * QKVN_ + 2 * DIM_ + h * HD_;
    for (int i = threadIdx.x; i < NTOK * HD_; i += 256) {
        int m = i >> 5, d = i & 31;
        Vs[i] = vb[(size_t)m * QKVN_ + d];
    }
    float2 s = sc[h];
    const float* tb = t + (size_t)bh * P_;
    float* ao = attn_out ? attn_out + (size_t)bh * P_ : (float*)0;
    __syncthreads();
    int d = threadIdx.x & 31, ch = threadIdx.x >> 5;
    for (int n = 0; n < NTOK; n++) {
        for (int i = threadIdx.x; i < NTOK; i += 256) {
            float v = fmaf(s.x, tb[n * NTOK + i], s.y);
            row[i] = v;
            if (ao) ao[n * NTOK + i] = v;
        }
        __syncthreads();
        float acc = 0.f;
        for (int m = ch; m < NTOK; m += 8) acc = fmaf(row[m], Vs[m * HD_ + d], acc);
        part[ch][d] = acc;
        __syncthreads();
        if (threadIdx.x < 32) {
            float r = 0.f;
#pragma unroll
            for (int c2 = 0; c2 < 8; c2++) r += part[c2][threadIdx.x];
            av[((size_t)(b * NTOK + n)) * DIM_ + h * HD_ + threadIdx.x] = r;
        }
        __syncthreads();
    }
}

// --------------------------------- launcher ----------------------------------
extern "C" void kernel_launch(void* const* d_in, const int* in_sizes, int n_in,
                              void* d_out, int out_size) {
    const float* x          = (const float*)d_in[0];
    const float* ln1_g      = (const float*)d_in[1];
    const float* ln1_b      = (const float*)d_in[2];
    const float* qkv_w      = (const float*)d_in[3];
    const float* conv_exp_w = (const float*)d_in[4];
    const float* bn1_g      = (const float*)d_in[5];
    const float* bn1_b      = (const float*)d_in[6];
    const float* dw_w       = (const float*)d_in[7];
    const float* bn2_g      = (const float*)d_in[8];
    const float* bn2_b      = (const float*)d_in[9];
    const float* conv_pro_w = (const float*)d_in[10];
    const float* bn3_g      = (const float*)d_in[11];
    const float* bn3_b      = (const float*)d_in[12];
    const float* abn_g      = (const float*)d_in[13];
    const float* abn_b      = (const float*)d_in[14];
    const float* proj_w     = (const float*)d_in[15];
    const float* proj_b     = (const float*)d_in[16];
    const float* ln2_g      = (const float*)d_in[17];
    const float* ln2_b      = (const float*)d_in[18];
    const float* fc1_w      = (const float*)d_in[19];
    const float* fc1_b      = (const float*)d_in[20];
    const float* fc2_w      = (const float*)d_in[21];
    const float* fc2_b      = (const float*)d_in[22];
    const float* scale_ch   = (const float*)d_in[23];

    void* p;
    cudaGetSymbolAddress(&p, g_h);    float*  hb    = (float*)p;
    cudaGetSymbolAddress(&p, g_qkv);  float*  qkvb  = (float*)p;
    cudaGetSymbolAddress(&p, g_attn); float*  attnb = (float*)p;
    cudaGetSymbolAddress(&p, g_aexp); float*  aexpb = (float*)p;
    cudaGetSymbolAddress(&p, g_adw);  float*  adwb  = (float*)p;
    cudaGetSymbolAddress(&p, g_apro); float*  aprob = (float*)p;
    cudaGetSymbolAddress(&p, g_av);   float*  avb   = (float*)p;
    cudaGetSymbolAddress(&p, g_x1);   float*  x1b   = (float*)p;
    cudaGetSymbolAddress(&p, g_m);    float*  mb    = (float*)p;
    cudaGetSymbolAddress(&p, g_mlp);  float*  mlpb  = (float*)p;
    cudaGetSymbolAddress(&p, g_stats);double* stats = (double*)p;
    cudaGetSymbolAddress(&p, g_sc);   float2* scb   = (float2*)p;

    const int XSZ = TOK_ * DIM_;             // 2,420,736
    const int ASZ = B_ * HEADS_ * P_;        // 14,902,656
    float* xout; float* attnout;
    if (out_size >= XSZ + ASZ)      { xout = (float*)d_out; attnout = (float*)d_out + XSZ; }
    else if (out_size >= ASZ)       { attnout = (float*)d_out; xout = hb; }  // attn-only (fallback)
    else                            { xout = (float*)d_out; attnout = (float*)0; }

    zero_stats_k<<<1, 288>>>(stats);

    // LN1 -> h
    ln_kernel<<<TOK_, 128>>>(x, ln1_g, ln1_b, hb);
    // qkv = h @ qkv_w^T
    gemm_nt<<<dim3(QKVN_ / 64, (TOK_ + 63) / 64), 256>>>(
        hb, qkv_w, qkvb, TOK_, QKVN_, DIM_, 0, 0, 0, 0);
    // attention logits + softmax
    attn_softmax_k<<<B_ * HEADS_, 256>>>(qkvb, attnb);

    // DLA refinement path
    conv_exp_k<<<(PIX_ + 255) / 256, 256>>>(attnb, conv_exp_w, aexpb);
    plane_stats<<<B_ * HID_, 256>>>(aexpb, stats + 0, HID_);
    bn_fin<<<1, HID_>>>(stats + 0, bn1_g, bn1_b, scb + 0, HID_);

    dwconv_k<<<dim3(7, 7, B_ * HID_), 256>>>(aexpb, dw_w, scb + 0, adwb);
    plane_stats<<<B_ * HID_, 256>>>(adwb, stats + 72, HID_);
    bn_fin<<<1, HID_>>>(stats + 72, bn2_g, bn2_b, scb + 36, HID_);

    conv_pro_k<<<(PIX_ + 255) / 256, 256>>>(adwb, conv_pro_w, scb + 36, aprob);
    plane_stats<<<B_ * HEADS_, 256>>>(aprob, stats + 144, HEADS_);
    bn_fin<<<1, HEADS_>>>(stats + 144, bn3_g, bn3_b, scb + 72, HEADS_);

    adapt_add_k<<<(ASZ + 255) / 256, 256>>>(aprob, attnb, scb + 72);
    plane_stats<<<B_ * HEADS_, 256>>>(aprob, stats + 216, HEADS_);
    bn_fin<<<1, HEADS_>>>(stats + 216, abn_g, abn_b, scb + 108, HEADS_);

    // attn (abn applied) @ V  -> av in [B,N,C]; also writes final attn output
    attn_av_k<<<B_ * HEADS_, 256>>>(aprob, qkvb, scb + 108, attnout, avb);

    // x1 = x + 2*(av @ proj_w^T + proj_b)
    gemm_nt<<<dim3(DIM_ / 64, (TOK_ + 63) / 64), 256>>>(
        avb, proj_w, x1b, TOK_, DIM_, DIM_, 1, proj_b, x, 0);
    // LN2 -> m
    ln_kernel<<<TOK_, 128>>>(x1b, ln2_g, ln2_b, mb);
    // fc1 + exact gelu
    gemm_nt<<<dim3(MLPH_ / 64, (TOK_ + 63) / 64), 256>>>(
        mb, fc1_w, mlpb, TOK_, MLPH_, DIM_, 2, fc1_b, 0, 0);
    // x_out = x1 + 2*scale_ch*(mlp @ fc2_w^T + fc2_b)
    gemm_nt<<<dim3(DIM_ / 64, (TOK_ + 63) / 64), 256>>>(
        mlpb, fc2_w, xout, TOK_, DIM_, MLPH_, 3, fc2_b, x1b, scale_ch);
}

// round 2
// speedup vs baseline: 1.0498x; 1.0498x over previous
#include <cuda_runtime.h>
#include <math.h>

#define B_     32
#define NTOK   197
#define DIM_   384
#define HEADS_ 12
#define HD_    32
#define HID_   36
#define P_     38809        // 197*197
#define TOK_   6304         // 32*197
#define QKVN_  1152
#define MLPH_  1536
#define PIX_   1241888      // 32*38809
#define CE_BLOCKS 592

// ------------------------- scratch (static device globals) -------------------
__device__ float  g_h   [TOK_ * DIM_];
__device__ float  g_qkv [TOK_ * QKVN_];
__device__ float  g_attn[(size_t)B_ * HEADS_ * P_];   // softmax output a0
__device__ float  g_aexp[(size_t)B_ * HID_   * P_];
__device__ float  g_adw [(size_t)B_ * HID_   * P_];
__device__ float  g_apro[(size_t)B_ * HEADS_ * P_];   // later holds t = bn3(a)+a0
__device__ float  g_av  [TOK_ * DIM_];
__device__ float  g_x1  [TOK_ * DIM_];
__device__ float  g_m   [TOK_ * DIM_];
__device__ float  g_mlp [TOK_ * MLPH_];
__device__ double g_stats[288];
__device__ float2 g_sc  [144];      // 4 regions of 36 float2 (scale, shift)

// ------------------------------- helpers -------------------------------------
__device__ __forceinline__ unsigned f2tf(float x) {
    unsigned r;
    asm("cvt.rna.tf32.f32 %0, %1;" : "=r"(r) : "f"(x));
    return r;
}

__global__ void zero_stats_k(double* st) {
    if (threadIdx.x < 288) st[threadIdx.x] = 0.0;
}

// LayerNorm of (0.5 * x). One block per token.
__global__ void ln_kernel(const float* __restrict__ x, const float* __restrict__ g,
                          const float* __restrict__ b, float* __restrict__ out) {
    int t = blockIdx.x, tid = threadIdx.x;
    const float* xr = x + (size_t)t * DIM_;
    float v0 = 0.5f * xr[tid];
    float v1 = 0.5f * xr[tid + 128];
    float v2 = 0.5f * xr[tid + 256];
    float s  = v0 + v1 + v2;
    float s2 = v0 * v0 + v1 * v1 + v2 * v2;
    for (int o = 16; o; o >>= 1) {
        s  += __shfl_down_sync(0xffffffffu, s,  o);
        s2 += __shfl_down_sync(0xffffffffu, s2, o);
    }
    __shared__ float sh[4][2];
    __shared__ float mv[2];
    if ((tid & 31) == 0) { sh[tid >> 5][0] = s; sh[tid >> 5][1] = s2; }
    __syncthreads();
    if (tid == 0) {
        float S = sh[0][0] + sh[1][0] + sh[2][0] + sh[3][0];
        float S2 = sh[0][1] + sh[1][1] + sh[2][1] + sh[3][1];
        float mean = S / (float)DIM_;
        float var  = S2 / (float)DIM_ - mean * mean;
        mv[0] = mean; mv[1] = rsqrtf(var + 1e-5f);
    }
    __syncthreads();
    float mean = mv[0], inv = mv[1];
    float* orow = out + (size_t)t * DIM_;
    orow[tid]       = (v0 - mean) * inv * g[tid]       + b[tid];
    orow[tid + 128] = (v1 - mean) * inv * g[tid + 128] + b[tid + 128];
    orow[tid + 256] = (v2 - mean) * inv * g[tid + 256] + b[tid + 256];
}

// --------------------------- tf32 tensor-core GEMM ---------------------------
// C[M,N] = A[M,K] * B[N,K]^T. 128x64 block, BK=32, 8 warps (4x2), warp 32x32.
// epi 0: plain   1: resid + 2*(acc+bias)   2: gelu(acc+bias)
// epi 3: resid + 2*scale[n]*(acc+bias)
__global__ __launch_bounds__(256) void gemm_tf32(
        const float* __restrict__ A, const float* __restrict__ Bm,
        float* __restrict__ C, int M, int N, int K, int epi,
        const float* __restrict__ bias, const float* __restrict__ resid,
        const float* __restrict__ scale) {
    __shared__ unsigned As[128][36];
    __shared__ unsigned Bs[64][36];
    int tid = threadIdx.x;
    int warp = tid >> 5, lane = tid & 31;
    int g = lane >> 2, tig = lane & 3;
    int wm = (warp & 3) * 32, wn = (warp >> 2) * 32;
    int m0 = blockIdx.y * 128, n0 = blockIdx.x * 64;

    float acc[2][4][4];
#pragma unroll
    for (int mi = 0; mi < 2; mi++)
#pragma unroll
        for (int nj = 0; nj < 4; nj++)
#pragma unroll
            for (int r = 0; r < 4; r++) acc[mi][nj][r] = 0.f;

    for (int k0 = 0; k0 < K; k0 += 32) {
#pragma unroll
        for (int i = 0; i < 4; i++) {
            int idx = tid + i * 256;
            int r = idx >> 3, c = (idx & 7) * 4;
            float4 v = make_float4(0.f, 0.f, 0.f, 0.f);
            if (m0 + r < M) v = *(const float4*)&A[(size_t)(m0 + r) * K + k0 + c];
            uint4 u;
            u.x = f2tf(v.x); u.y = f2tf(v.y); u.z = f2tf(v.z); u.w = f2tf(v.w);
            *(uint4*)&As[r][c] = u;
        }
#pragma unroll
        for (int i = 0; i < 2; i++) {
            int idx = tid + i * 256;
            int r = idx >> 3, c = (idx & 7) * 4;
            float4 v = *(const float4*)&Bm[(size_t)(n0 + r) * K + k0 + c];
            uint4 u;
            u.x = f2tf(v.x); u.y = f2tf(v.y); u.z = f2tf(v.z); u.w = f2tf(v.w);
            *(uint4*)&Bs[r][c] = u;
        }
        __syncthreads();
#pragma unroll
        for (int ks = 0; ks < 4; ks++) {
            unsigned a[2][4], bfr[4][2];
#pragma unroll
            for (int mi = 0; mi < 2; mi++) {
                int rr = wm + mi * 16 + g;
                a[mi][0] = As[rr][ks * 8 + tig];
                a[mi][1] = As[rr + 8][ks * 8 + tig];
                a[mi][2] = As[rr][ks * 8 + tig + 4];
                a[mi][3] = As[rr + 8][ks * 8 + tig + 4];
            }
#pragma unroll
            for (int nj = 0; nj < 4; nj++) {
                int cc = wn + nj * 8 + g;
                bfr[nj][0] = Bs[cc][ks * 8 + tig];
                bfr[nj][1] = Bs[cc][ks * 8 + tig + 4];
            }
#pragma unroll
            for (int mi = 0; mi < 2; mi++)
#pragma unroll
                for (int nj = 0; nj < 4; nj++) {
                    asm volatile(
                        "mma.sync.aligned.m16n8k8.row.col.f32.tf32.tf32.f32 "
                        "{%0,%1,%2,%3},{%4,%5,%6,%7},{%8,%9},{%0,%1,%2,%3};"
                        : "+f"(acc[mi][nj][0]), "+f"(acc[mi][nj][1]),
                          "+f"(acc[mi][nj][2]), "+f"(acc[mi][nj][3])
                        : "r"(a[mi][0]), "r"(a[mi][1]), "r"(a[mi][2]), "r"(a[mi][3]),
                          "r"(bfr[nj][0]), "r"(bfr[nj][1]));
                }
        }
        __syncthreads();
    }
    // epilogue
#pragma unroll
    for (int mi = 0; mi < 2; mi++) {
#pragma unroll
        for (int half = 0; half < 2; half++) {
            int row = m0 + wm + mi * 16 + g + half * 8;
            if (row >= M) continue;
#pragma unroll
            for (int nj = 0; nj < 4; nj++) {
                int col = n0 + wn + nj * 8 + 2 * tig;
                float v0 = acc[mi][nj][half * 2 + 0];
                float v1 = acc[mi][nj][half * 2 + 1];
                size_t o = (size_t)row * N + col;
                if (epi == 0) {
                    *(float2*)&C[o] = make_float2(v0, v1);
                } else if (epi == 1) {
                    float r0 = resid[o], r1 = resid[o + 1];
                    *(float2*)&C[o] = make_float2(r0 + 2.f * (v0 + bias[col]),
                                                  r1 + 2.f * (v1 + bias[col + 1]));
                } else if (epi == 2) {
                    float u0 = v0 + bias[col], u1 = v1 + bias[col + 1];
                    u0 = 0.5f * u0 * (1.f + erff(u0 * 0.70710678118654752f));
                    u1 = 0.5f * u1 * (1.f + erff(u1 * 0.70710678118654752f));
                    *(float2*)&C[o] = make_float2(u0, u1);
                } else {
                    float u0 = (v0 + bias[col]) * scale[col];
                    float u1 = (v1 + bias[col + 1]) * scale[col + 1];
                    *(float2*)&C[o] = make_float2(resid[o] + 2.f * u0,
                                                  resid[o + 1] + 2.f * u1);
                }
            }
        }
    }
}

// --------------------- attention logits + softmax (fused) --------------------
__global__ void attn_softmax_k(const float* __restrict__ qkv, float* __restrict__ attn) {
    int bh = blockIdx.x, b = bh / HEADS_, h = bh - b * HEADS_;
    __shared__ float Ks[32 * 227];
    const float* base = qkv + (size_t)b * NTOK * QKVN_ + h * HD_;
    for (int i = threadIdx.x; i < NTOK * 32; i += 256) {
        int m = i >> 5, d = i & 31;
        Ks[d * 227 + m] = base[(size_t)m * QKVN_ + DIM_ + d];
    }
    __syncthreads();
    int lane = threadIdx.x & 31, w = threadIdx.x >> 5;
    float* arow = attn + (size_t)bh * P_;
    for (int n = w; n < NTOK; n += 8) {
        float qreg = base[(size_t)n * QKVN_ + lane];
        float a[7] = {0, 0, 0, 0, 0, 0, 0};
#pragma unroll
        for (int d = 0; d < 32; d++) {
            float qv = __shfl_sync(0xffffffffu, qreg, d);
            const float* kc = &Ks[d * 227 + lane];
#pragma unroll
            for (int j = 0; j < 7; j++) a[j] = fmaf(qv, kc[j * 32], a[j]);
        }
#pragma unroll
        for (int j = 0; j < 7; j++) a[j] *= 0.17677669529663689f;
        if (lane >= 5) a[6] = -INFINITY;
        float mx = a[0];
#pragma unroll
        for (int j = 1; j < 7; j++) mx = fmaxf(mx, a[j]);
        for (int o = 16; o; o >>= 1) mx = fmaxf(mx, __shfl_xor_sync(0xffffffffu, mx, o));
        float sum = 0.f;
#pragma unroll
        for (int j = 0; j < 7; j++) { a[j] = expf(a[j] - mx); sum += a[j]; }
        for (int o = 16; o; o >>= 1) sum += __shfl_xor_sync(0xffffffffu, sum, o);
        float inv = 1.f / sum;
#pragma unroll
        for (int j = 0; j < 7; j++) {
            int m = lane + 32 * j;
            if (m < NTOK) arow[(size_t)n * NTOK + m] = a[j] * inv;
        }
    }
}

// -------------------- conv_exp (1x1 12->36) + fused bn1 sumsq ----------------
__global__ __launch_bounds__(256) void conv_exp_k(const float* __restrict__ attn,
        const float* __restrict__ w, float* __restrict__ aexp, double* __restrict__ sums) {
    __shared__ float ws[HID_ * HEADS_];
    int tid = threadIdx.x;
    for (int i = tid; i < HID_ * HEADS_; i += 256) ws[i] = w[i];
    __syncthreads();
    float ssq[HID_];
#pragma unroll
    for (int o = 0; o < HID_; o++) ssq[o] = 0.f;
    for (int idx = blockIdx.x * 256 + tid; idx < PIX_; idx += CE_BLOCKS * 256) {
        int b = idx / P_, p = idx - b * P_;
        const float* ap = attn + (size_t)b * HEADS_ * P_ + p;
        float in[HEADS_];
#pragma unroll
        for (int i = 0; i < HEADS_; i++) in[i] = ap[(size_t)i * P_];
        float* op = aexp + (size_t)b * HID_ * P_ + p;
#pragma unroll
        for (int o = 0; o < HID_; o++) {
            float v = 0.f;
#pragma unroll
            for (int i = 0; i < HEADS_; i++) v = fmaf(ws[o * HEADS_ + i], in[i], v);
            op[(size_t)o * P_] = v;
            ssq[o] = fmaf(v, v, ssq[o]);
        }
    }
    // reduce ssq
    int lane = tid & 31, wp = tid >> 5;
    __shared__ float red[8][HID_];
#pragma unroll
    for (int o = 0; o < HID_; o++) {
        float v = ssq[o];
        for (int off = 16; off; off >>= 1) v += __shfl_down_sync(0xffffffffu, v, off);
        if (lane == 0) red[wp][o] = v;
    }
    __syncthreads();
    if (tid < HID_) {
        float s = 0.f;
#pragma unroll
        for (int i = 0; i < 8; i++) s += red[i][tid];
        atomicAdd(&sums[tid], (double)s);
    }
}

// depthwise 3x3 SAME; bn1 affine + relu6 at load; fused bn2 sum/sumsq
__global__ void dwconv_k(const float* __restrict__ aexp, const float* __restrict__ dww,
                         const float2* __restrict__ sc, float* __restrict__ adw,
                         double* __restrict__ sums) {
    int bz = blockIdx.z, b = bz / HID_, c = bz - b * HID_;
    __shared__ float tile[34][34];
    float2 s = sc[c];
    const float* ip = aexp + ((size_t)b * HID_ + c) * P_;
    int y0 = blockIdx.y * 32, x0 = blockIdx.x * 32;
    for (int i = threadIdx.x; i < 34 * 34; i += 256) {
        int ly = i / 34, lx = i - ly * 34;
        int gy = y0 + ly - 1, gx = x0 + lx - 1;
        float v = 0.f;
        if (gy >= 0 && gy < NTOK && gx >= 0 && gx < NTOK) {
            v = fmaf(s.x, ip[gy * NTOK + gx], s.y);
            v = fminf(fmaxf(v, 0.f), 6.f);
        }
        tile[ly][lx] = v;
    }
    float w[9];
#pragma unroll
    for (int k = 0; k < 9; k++) w[k] = dww[c * 9 + k];
    __syncthreads();
    int tx = threadIdx.x & 31, tyb = threadIdx.x >> 5;
    float* op = adw + ((size_t)b * HID_ + c) * P_;
    float ls = 0.f, ls2 = 0.f;
#pragma unroll
    for (int r = 0; r < 4; r++) {
        int oy = tyb + r * 8;
        int gy = y0 + oy, gx = x0 + tx;
        if (gy < NTOK && gx < NTOK) {
            float a2 = 0.f;
#pragma unroll
            for (int dy = 0; dy < 3; dy++)
#pragma unroll
                for (int dx = 0; dx < 3; dx++)
                    a2 = fmaf(w[dy * 3 + dx], tile[oy + dy][tx + dx], a2);
            op[gy * NTOK + gx] = a2;
            ls += a2;
            ls2 = fmaf(a2, a2, ls2);
        }
    }
    int lane = threadIdx.x & 31, wp = threadIdx.x >> 5;
    for (int o = 16; o; o >>= 1) {
        ls  += __shfl_down_sync(0xffffffffu, ls,  o);
        ls2 += __shfl_down_sync(0xffffffffu, ls2, o);
    }
    __shared__ float rs[8], rs2[8];
    if (lane == 0) { rs[wp] = ls; rs2[wp] = ls2; }
    __syncthreads();
    if (threadIdx.x == 0) {
        float S = 0.f, S2 = 0.f;
#pragma unroll
        for (int i = 0; i < 8; i++) { S += rs[i]; S2 += rs2[i]; }
        atomicAdd(&sums[c], (double)S);
        atomicAdd(&sums[HID_ + c], (double)S2);
    }
}

// 1x1 project 36->12; bn2 affine+relu6 on inputs; fused bn3 sum/sumsq
__global__ __launch_bounds__(256) void conv_pro_k(const float* __restrict__ adw,
        const float* __restrict__ w, const float2* __restrict__ sc,
        float* __restrict__ apro, double* __restrict__ sums) {
    __shared__ float ws[HEADS_ * HID_];
    __shared__ float2 scs[HID_];
    int tid = threadIdx.x;
    for (int i = tid; i < HEADS_ * HID_; i += 256) ws[i] = w[i];
    if (tid < HID_) scs[tid] = sc[tid];
    __syncthreads();
    float ssum[HEADS_], ssq[HEADS_];
#pragma unroll
    for (int o = 0; o < HEADS_; o++) { ssum[o] = 0.f; ssq[o] = 0.f; }
    for (int idx = blockIdx.x * 256 + tid; idx < PIX_; idx += CE_BLOCKS * 256) {
        int b = idx / P_, p = idx - b * P_;
        const float* ip = adw + (size_t)b * HID_ * P_ + p;
        float in[HID_];
#pragma unroll
        for (int i = 0; i < HID_; i++) {
            float2 s = scs[i];
            float v = fmaf(s.x, ip[(size_t)i * P_], s.y);
            in[i] = fminf(fmaxf(v, 0.f), 6.f);
        }
        float* op = apro + (size_t)b * HEADS_ * P_ + p;
#pragma unroll
        for (int o = 0; o < HEADS_; o++) {
            float v = 0.f;
#pragma unroll
            for (int i = 0; i < HID_; i++) v = fmaf(ws[o * HID_ + i], in[i], v);
            op[(size_t)o * P_] = v;
            ssum[o] += v;
            ssq[o] = fmaf(v, v, ssq[o]);
        }
    }
    int lane = tid & 31, wp = tid >> 5;
    __shared__ float red[8][24];
#pragma unroll
    for (int o = 0; o < HEADS_; o++) {
        float v = ssum[o], v2 = ssq[o];
        for (int off = 16; off; off >>= 1) {
            v  += __shfl_down_sync(0xffffffffu, v,  off);
            v2 += __shfl_down_sync(0xffffffffu, v2, off);
        }
        if (lane == 0) { red[wp][o] = v; red[wp][HEADS_ + o] = v2; }
    }
    __syncthreads();
    if (tid < 24) {
        float s = 0.f;
#pragma unroll
        for (int i = 0; i < 8; i++) s += red[i][tid];
        atomicAdd(&sums[tid], (double)s);
    }
}

// t = bn3(a_pro) + a0 (in place); fused abn stats. grid (38, B*HEADS)
__global__ void adapt_add_k(float* __restrict__ t, const float* __restrict__ a0,
                            const float2* __restrict__ sc, double* __restrict__ sums) {
    int pl = blockIdx.y;
    int c = pl % HEADS_;
    float2 s = sc[c];
    size_t base = (size_t)pl * P_;
    float ls = 0.f, ls2 = 0.f;
#pragma unroll
    for (int i = 0; i < 4; i++) {
        int p = blockIdx.x * 1024 + i * 256 + threadIdx.x;
        if (p < P_) {
            float v = fmaf(s.x, t[base + p], s.y) + a0[base + p];
            t[base + p] = v;
            ls += v;
            ls2 = fmaf(v, v, ls2);
        }
    }
    int lane = threadIdx.x & 31, wp = threadIdx.x >> 5;
    for (int o = 16; o; o >>= 1) {
        ls  += __shfl_down_sync(0xffffffffu, ls,  o);
        ls2 += __shfl_down_sync(0xffffffffu, ls2, o);
    }
    __shared__ float rs[8], rs2[8];
    if (lane == 0) { rs[wp] = ls; rs2[wp] = ls2; }
    __syncthreads();
    if (threadIdx.x == 0) {
        float S = 0.f, S2 = 0.f;
#pragma unroll
        for (int i = 0; i < 8; i++) { S += rs[i]; S2 += rs2[i]; }
        atomicAdd(&sums[c], (double)S);
        atomicAdd(&sums[HEADS_ + c], (double)S2);
    }
}

// ------------------------------ BN finalize ----------------------------------
__global__ void bn_fin(const double* __restrict__ sums, const float* __restrict__ g,
                       const float* __restrict__ b, float2* __restrict__ sc, int C) {
    int c = threadIdx.x;
    if (c >= C) return;
    const double cnt = 1241888.0;
    double mean = sums[c] / cnt;
    double var  = sums[C + c] / cnt - mean * mean;
    float s = (float)((double)g[c] / sqrt(var + 1e-5));
    sc[c] = make_float2(s, (float)((double)b[c] - mean * (double)s));
}

// bn1: mean analytic from conv_exp_w (softmax rows sum to 1)
__global__ void bn_fin1(const double* __restrict__ sumsq, const float* __restrict__ w,
                        const float* __restrict__ g, const float* __restrict__ b,
                        float2* __restrict__ sc) {
    int c = threadIdx.x;
    if (c >= HID_) return;
    float rs = 0.f;
#pragma unroll
    for (int i = 0; i < HEADS_; i++) rs += w[c * HEADS_ + i];
    double mean = (double)rs / 197.0;
    double var  = sumsq[c] / 1241888.0 - mean * mean;
    float s = (float)((double)g[c] / sqrt(var + 1e-5));
    sc[c] = make_float2(s, (float)((double)b[c] - mean * (double)s));
}

// ------------------- attn*V + abn apply + attn output ------------------------
__global__ __launch_bounds__(256) void attn_av_k(const float* __restrict__ t,
        const float* __restrict__ qkv, const float2* __restrict__ sc,
        float* __restrict__ attn_out, float* __restrict__ av) {
    int bh = blockIdx.x, b = bh / HEADS_, h = bh - b * HEADS_;
    __shared__ float Vs[NTOK * 33];
    const float* vb = qkv + (size_t)b * NTOK * QKVN_ + 2 * DIM_ + h * HD_;
    int tid = threadIdx.x;
    for (int i = tid; i < NTOK * 32; i += 256) {
        int m = i >> 5, d = i & 31;
        Vs[m * 33 + d] = vb[(size_t)m * QKVN_ + d];
    }
    float2 s = sc[h];
    const float* tb = t + (size_t)bh * P_;
    float* ao = attn_out ? attn_out + (size_t)bh * P_ : (float*)0;
    __syncthreads();
    int lane = tid & 31, w = tid >> 5;
    for (int n = w; n < NTOK; n += 8) {
        const float* trow = tb + n * NTOK;
        float acc = 0.f;
#pragma unroll
        for (int mb = 0; mb < 192; mb += 32) {
            float tv = fmaf(s.x, trow[mb + lane], s.y);
            if (ao) ao[n * NTOK + mb + lane] = tv;
#pragma unroll
            for (int j = 0; j < 32; j++) {
                float bv = __shfl_sync(0xffffffffu, tv, j);
                acc = fmaf(bv, Vs[(mb + j) * 33 + lane], acc);
            }
        }
        {
            float tv = (lane < 5) ? fmaf(s.x, trow[192 + lane], s.y) : 0.f;
            if (ao && lane < 5) ao[n * NTOK + 192 + lane] = tv;
#pragma unroll
            for (int j = 0; j < 5; j++) {
                float bv = __shfl_sync(0xffffffffu, tv, j);
                acc = fmaf(bv, Vs[(192 + j) * 33 + lane], acc);
            }
        }
        av[((size_t)(b * NTOK + n)) * DIM_ + h * HD_ + lane] = acc;
    }
}

// --------------------------------- launcher ----------------------------------
extern "C" void kernel_launch(void* const* d_in, const int* in_sizes, int n_in,
                              void* d_out, int out_size) {
    const float* x          = (const float*)d_in[0];
    const float* ln1_g      = (const float*)d_in[1];
    const float* ln1_b      = (const float*)d_in[2];
    const float* qkv_w      = (const float*)d_in[3];
    const float* conv_exp_w = (const float*)d_in[4];
    const float* bn1_g      = (const float*)d_in[5];
    const float* bn1_b      = (const float*)d_in[6];
    const float* dw_w       = (const float*)d_in[7];
    const float* bn2_g      = (const float*)d_in[8];
    const float* bn2_b      = (const float*)d_in[9];
    const float* conv_pro_w = (const float*)d_in[10];
    const float* bn3_g      = (const float*)d_in[11];
    const float* bn3_b      = (const float*)d_in[12];
    const float* abn_g      = (const float*)d_in[13];
    const float* abn_b      = (const float*)d_in[14];
    const float* proj_w     = (const float*)d_in[15];
    const float* proj_b     = (const float*)d_in[16];
    const float* ln2_g      = (const float*)d_in[17];
    const float* ln2_b      = (const float*)d_in[18];
    const float* fc1_w      = (const float*)d_in[19];
    const float* fc1_b      = (const float*)d_in[20];
    const float* fc2_w      = (const float*)d_in[21];
    const float* fc2_b      = (const float*)d_in[22];
    const float* scale_ch   = (const float*)d_in[23];

    void* p;
    cudaGetSymbolAddress(&p, g_h);    float*  hb    = (float*)p;
    cudaGetSymbolAddress(&p, g_qkv);  float*  qkvb  = (float*)p;
    cudaGetSymbolAddress(&p, g_attn); float*  attnb = (float*)p;
    cudaGetSymbolAddress(&p, g_aexp); float*  aexpb = (float*)p;
    cudaGetSymbolAddress(&p, g_adw);  float*  adwb  = (float*)p;
    cudaGetSymbolAddress(&p, g_apro); float*  aprob = (float*)p;
    cudaGetSymbolAddress(&p, g_av);   float*  avb   = (float*)p;
    cudaGetSymbolAddress(&p, g_x1);   float*  x1b   = (float*)p;
    cudaGetSymbolAddress(&p, g_m);    float*  mb    = (float*)p;
    cudaGetSymbolAddress(&p, g_mlp);  float*  mlpb  = (float*)p;
    cudaGetSymbolAddress(&p, g_stats);double* stats = (double*)p;
    cudaGetSymbolAddress(&p, g_sc);   float2* scb   = (float2*)p;

    const int XSZ = TOK_ * DIM_;
    const int ASZ = B_ * HEADS_ * P_;
    float* xout; float* attnout;
    if (out_size >= XSZ + ASZ)      { xout = (float*)d_out; attnout = (float*)d_out + XSZ; }
    else if (out_size >= ASZ)       { attnout = (float*)d_out; xout = hb; }
    else                            { xout = (float*)d_out; attnout = (float*)0; }

    zero_stats_k<<<1, 288>>>(stats);

    ln_kernel<<<TOK_, 128>>>(x, ln1_g, ln1_b, hb);
    gemm_tf32<<<dim3(QKVN_ / 64, (TOK_ + 127) / 128), 256>>>(
        hb, qkv_w, qkvb, TOK_, QKVN_, DIM_, 0, 0, 0, 0);
    attn_softmax_k<<<B_ * HEADS_, 256>>>(qkvb, attnb);

    conv_exp_k<<<CE_BLOCKS, 256>>>(attnb, conv_exp_w, aexpb, stats + 0);
    bn_fin1<<<1, HID_>>>(stats + 0, conv_exp_w, bn1_g, bn1_b, scb + 0);

    dwconv_k<<<dim3(7, 7, B_ * HID_), 256>>>(aexpb, dw_w, scb + 0, adwb, stats + 72);
    bn_fin<<<1, HID_>>>(stats + 72, bn2_g, bn2_b, scb + 36, HID_);

    conv_pro_k<<<CE_BLOCKS, 256>>>(adwb, conv_pro_w, scb + 36, aprob, stats + 144);
    bn_fin<<<1, HEADS_>>>(stats + 144, bn3_g, bn3_b, scb + 72, HEADS_);

    adapt_add_k<<<dim3(38, B_ * HEADS_), 256>>>(aprob, attnb, scb + 72, stats + 216);
    bn_fin<<<1, HEADS_>>>(stats + 216, abn_g, abn_b, scb + 108, HEADS_);

    attn_av_k<<<B_ * HEADS_, 256>>>(aprob, qkvb, scb + 108, attnout, avb);

    gemm_tf32<<<dim3(DIM_ / 64, (TOK_ + 127) / 128), 256>>>(
        avb, proj_w, x1b, TOK_, DIM_, DIM_, 1, proj_b, x, 0);
    ln_kernel<<<TOK_, 128>>>(x1b, ln2_g, ln2_b, mb);
    gemm_tf32<<<dim3(MLPH_ / 64, (TOK_ + 127) / 128), 256>>>(
        mb, fc1_w, mlpb, TOK_, MLPH_, DIM_, 2, fc1_b, 0, 0);
    gemm_tf32<<<dim3(DIM_ / 64, (TOK_ + 127) / 128), 256>>>(
        mlpb, fc2_w, xout, TOK_, DIM_, MLPH_, 3, fc2_b, x1b, scale_ch);
}